// round 11
// baseline (speedup 1.0000x reference)
#include <cuda_runtime.h>
#include <cuda_bf16.h>
#include <math.h>
#include <stdint.h>

#define BB 512
#define DD 768
#define HH 384
#define KP1 2304   // 3 * 768  (extended K for stage 1)
#define KP2 1152   // 3 * 384  (extended K for stage 2)

// -------------------- device scratch (allocation-free rule) -----------------
__device__ __align__(16) __nv_bfloat16 g_Xext[BB * KP1];       // [Xh|Xh|Xl]
__device__ __align__(16) __nv_bfloat16 g_W1T[2][HH * KP1];     // [z][n][Wh|Wl|Wh]
__device__ __align__(16) __nv_bfloat16 g_W2T[2][DD * KP2];     // [z][n][Wh|Wl|Wh]
__device__ __align__(16) __nv_bfloat16 g_Hext[2][BB * KP2];    // [z][Hh|Hh|Hl]
__device__ __align__(16) float g_part1[6 * 2 * BB * HH];       // stage1 split-K partials
__device__ __align__(16) float g_part2[3 * 2 * BB * DD];       // stage2 split-K partials
__device__ __align__(16) float g_Syp[8][DD];
__device__ __align__(16) float g_Sy2p[8][DD];
__device__ __align__(16) float g_Sy[DD];
__device__ __align__(16) float g_Sy2[DD];
__device__ double g_acc[2];
__device__ unsigned g_done;

// -------------------- helpers ----------------------------------------------
__device__ __forceinline__ uint32_t smem_u32(const void* p) {
    uint32_t a;
    asm("{ .reg .u64 t; cvta.to.shared.u64 t, %1; cvt.u32.u64 %0, t; }" : "=r"(a) : "l"(p));
    return a;
}
__device__ __forceinline__ void cp_async16(uint32_t s, const void* g) {
    asm volatile("cp.async.cg.shared.global [%0], [%1], 16;\n" :: "r"(s), "l"(g));
}
__device__ __forceinline__ void cp_commit() { asm volatile("cp.async.commit_group;" ::: "memory"); }
__device__ __forceinline__ void cp_wait0()  { asm volatile("cp.async.wait_group 0;" ::: "memory"); }
__device__ __forceinline__ void cp_wait1()  { asm volatile("cp.async.wait_group 1;" ::: "memory"); }

__device__ __forceinline__ void ldmx4(uint32_t* r, uint32_t addr) {
    asm volatile("ldmatrix.sync.aligned.m8n8.x4.shared.b16 {%0,%1,%2,%3}, [%4];"
                 : "=r"(r[0]), "=r"(r[1]), "=r"(r[2]), "=r"(r[3]) : "r"(addr));
}
__device__ __forceinline__ void mma16816(float* c, const uint32_t* a,
                                         uint32_t b0, uint32_t b1) {
    asm volatile("mma.sync.aligned.m16n8k16.row.col.f32.bf16.bf16.f32 "
                 "{%0,%1,%2,%3}, {%4,%5,%6,%7}, {%8,%9}, {%0,%1,%2,%3};"
                 : "+f"(c[0]), "+f"(c[1]), "+f"(c[2]), "+f"(c[3])
                 : "r"(a[0]), "r"(a[1]), "r"(a[2]), "r"(a[3]), "r"(b0), "r"(b1));
}
__device__ __forceinline__ void bf16split(float v, __nv_bfloat16& h, __nv_bfloat16& l) {
    h = __float2bfloat16(v);
    l = __float2bfloat16(v - __bfloat162float(h));
}

// ---------------------------------------------------------------------------
// prep: Xext split; W1,W2 transpose+split into [N][K'] ext layout;
//       ystats partials; accumulator init.  grid: 1561 x 256.
// ---------------------------------------------------------------------------
__global__ void __launch_bounds__(256)
prep(const float* __restrict__ x, const float* __restrict__ y,
     const float* __restrict__ mu_w1, const float* __restrict__ lv_w1,
     const float* __restrict__ mu_w2, const float* __restrict__ lv_w2)
{
    const int bid = blockIdx.x, tid = threadIdx.x;
    __shared__ float ts[32][33];

    if (bid < 384) {                       // X split: one float4 per thread
        const int i4 = bid * 256 + tid;    // < 98304
        const int row = i4 / 192;
        const int cols = (i4 % 192) * 4;
        float4 v = ((const float4*)x)[i4];
        __nv_bfloat16 h0,l0,h1,l1,h2,l2,h3,l3;
        bf16split(v.x,h0,l0); bf16split(v.y,h1,l1);
        bf16split(v.z,h2,l2); bf16split(v.w,h3,l3);
        __nv_bfloat162 ph0; ph0.x=h0; ph0.y=h1;
        __nv_bfloat162 ph1; ph1.x=h2; ph1.y=h3;
        __nv_bfloat162 pl0; pl0.x=l0; pl0.y=l1;
        __nv_bfloat162 pl1; pl1.x=l2; pl1.y=l3;
        __nv_bfloat16* R = g_Xext + (size_t)row * KP1;
        ((__nv_bfloat162*)(R + cols))[0] = ph0;        // Ah @ [0,768)
        ((__nv_bfloat162*)(R + cols))[1] = ph1;
        ((__nv_bfloat162*)(R + 768 + cols))[0] = ph0;  // Ah @ [768,1536)
        ((__nv_bfloat162*)(R + 768 + cols))[1] = ph1;
        ((__nv_bfloat162*)(R + 1536 + cols))[0] = pl0; // Al @ [1536,2304)
        ((__nv_bfloat162*)(R + 1536 + cols))[1] = pl1;
    } else if (bid < 960) {                // W1 [768k][384n] -> T [384][2304]
        const int t = bid - 384;
        const int z = t / 288, tt = t % 288;
        const int kt = tt / 12, nt = tt % 12;
        const int k0 = kt * 32, n0 = nt * 32;
        const float* W = z ? lv_w1 : mu_w1;
        #pragma unroll
        for (int u = 0; u < 4; u++) {
            int r = (tid >> 5) + u * 8, c = tid & 31;
            ts[r][c] = W[(k0 + r) * HH + n0 + c];
        }
        __syncthreads();
        #pragma unroll
        for (int u = 0; u < 4; u++) {
            int r = (tid >> 5) + u * 8, c = tid & 31;
            __nv_bfloat16 h, l;
            bf16split(ts[c][r], h, l);          // = W[k0+c][n0+r]
            __nv_bfloat16* R = g_W1T[z] + (size_t)(n0 + r) * KP1;
            R[k0 + c] = h;                       // Bh
            R[768 + k0 + c] = l;                 // Bl
            R[1536 + k0 + c] = h;                // Bh
        }
    } else if (bid < 1536) {               // W2 [384k][768n] -> T [768][1152]
        const int t = bid - 960;
        const int z = t / 288, tt = t % 288;
        const int kt = tt / 24, nt = tt % 24;
        const int k0 = kt * 32, n0 = nt * 32;
        const float* W = z ? lv_w2 : mu_w2;
        #pragma unroll
        for (int u = 0; u < 4; u++) {
            int r = (tid >> 5) + u * 8, c = tid & 31;
            ts[r][c] = W[(k0 + r) * DD + n0 + c];
        }
        __syncthreads();
        #pragma unroll
        for (int u = 0; u < 4; u++) {
            int r = (tid >> 5) + u * 8, c = tid & 31;
            __nv_bfloat16 h, l;
            bf16split(ts[c][r], h, l);
            __nv_bfloat16* R = g_W2T[z] + (size_t)(n0 + r) * KP2;
            R[k0 + c] = h;
            R[384 + k0 + c] = l;
            R[768 + k0 + c] = h;
        }
    } else if (bid < 1560) {               // ystats partials: 24 units
        const int unit = bid - 1536;
        const int rc = unit / 3, cb = unit % 3;
        const int d = cb * 256 + tid;
        float s = 0.0f, s2 = 0.0f;
        const int j0 = rc * 64;
        #pragma unroll 4
        for (int j = j0; j < j0 + 64; j++) {
            float v = y[j * DD + d];
            s += v;
            s2 = fmaf(v, v, s2);
        }
        g_Syp[rc][d] = s;
        g_Sy2p[rc][d] = s2;
    } else {
        if (tid == 0) { g_acc[0] = 0.0; g_acc[1] = 0.0; g_done = 0u; }
    }
}

// ---------------------------------------------------------------------------
// bf16 mma.sync GEMM, split-K.  128x128 CTA tile, 256 threads (8 warps),
// warp tile 64x32 (4 x m16, 4 x n8).  K slab = 32, cp.async double buffer.
//   C_part[s][z] = Aext[128 rows] @ BextT[K'-chunk s]   (raw fp32 partials)
// smem rows padded to 80B -> ldmatrix conflict-free.
// ---------------------------------------------------------------------------
template <int N, int KP, int SK, int STAGE>
__global__ void __launch_bounds__(256)
gemm_mma(void)
{
    constexpr int MT = BB / 128;
    constexpr int CHUNK = KP / SK;          // 384
    constexpr int NSLAB = CHUNK / 32;       // 12
    const int tid = threadIdx.x;
    const int z = blockIdx.z;
    const int mTile = blockIdx.y % MT;
    const int s     = blockIdx.y / MT;
    const int rowBase = mTile * 128;
    const int colBase = blockIdx.x * 128;
    const int kBase   = s * CHUNK;

    const __nv_bfloat16* __restrict__ A =
        (STAGE == 1) ? g_Xext : g_Hext[z];
    const __nv_bfloat16* __restrict__ Bm =
        (STAGE == 1) ? g_W1T[z] : g_W2T[z];
    float* __restrict__ C = (STAGE == 1)
        ? (g_part1 + (size_t)(s * 2 + z) * (BB * HH))
        : (g_part2 + (size_t)(s * 2 + z) * ((size_t)BB * DD));

    __shared__ __align__(16) char sm[2][2][10240];   // [buf][A/B], 80B rows
    const uint32_t sb = smem_u32(sm);

    const int warp = tid >> 5, lane = tid & 31;
    const int wm = warp >> 2, wn = warp & 3;         // warp grid 2x4
    const int g8 = lane >> 2, tig = lane & 3;
    const uint32_t lrow = (uint32_t)((lane & 15) * 80 + (lane >> 4) * 16);

    // cp.async mapping: 2 x 16B for A, 2 x 16B for B per thread per slab
    const int r0 = tid >> 2, sg0 = (tid & 3);
    const int r1 = (tid + 256) >> 2, sg1 = ((tid + 256) & 3);

    auto load_slab = [&](int slab, int buf) {
        const int k0 = kBase + slab * 32;
        const uint32_t Ad = sb + buf * 20480;
        const uint32_t Bd = Ad + 10240;
        cp_async16(Ad + r0 * 80 + sg0 * 16, A + (size_t)(rowBase + r0) * KP + k0 + sg0 * 8);
        cp_async16(Ad + r1 * 80 + sg1 * 16, A + (size_t)(rowBase + r1) * KP + k0 + sg1 * 8);
        cp_async16(Bd + r0 * 80 + sg0 * 16, Bm + (size_t)(colBase + r0) * KP + k0 + sg0 * 8);
        cp_async16(Bd + r1 * 80 + sg1 * 16, Bm + (size_t)(colBase + r1) * KP + k0 + sg1 * 8);
        cp_commit();
    };

    float acc[4][4][4];
    #pragma unroll
    for (int mi = 0; mi < 4; mi++)
        #pragma unroll
        for (int ni = 0; ni < 4; ni++)
            #pragma unroll
            for (int p = 0; p < 4; p++) acc[mi][ni][p] = 0.0f;

    load_slab(0, 0);

    #pragma unroll 1
    for (int sl = 0; sl < NSLAB; sl++) {
        const int buf = sl & 1;
        if (sl + 1 < NSLAB) { load_slab(sl + 1, buf ^ 1); cp_wait1(); }
        else                { cp_wait0(); }
        __syncthreads();

        const uint32_t Ab = sb + buf * 20480;
        const uint32_t Bb = Ab + 10240;
        #pragma unroll
        for (int t = 0; t < 2; t++) {
            uint32_t a[4][4], b[2][4];
            #pragma unroll
            for (int mi = 0; mi < 4; mi++)
                ldmx4(a[mi], Ab + (uint32_t)((wm * 64 + mi * 16) * 80 + t * 32) + lrow);
            #pragma unroll
            for (int ng = 0; ng < 2; ng++)
                ldmx4(b[ng], Bb + (uint32_t)((wn * 32 + ng * 16) * 80 + t * 32) + lrow);
            #pragma unroll
            for (int mi = 0; mi < 4; mi++) {
                mma16816(acc[mi][0], a[mi], b[0][0], b[0][2]);
                mma16816(acc[mi][1], a[mi], b[0][1], b[0][3]);
                mma16816(acc[mi][2], a[mi], b[1][0], b[1][2]);
                mma16816(acc[mi][3], a[mi], b[1][1], b[1][3]);
            }
        }
        __syncthreads();
    }

    // ---- epilogue: raw fp32 partials ----
    #pragma unroll
    for (int mi = 0; mi < 4; mi++) {
        const int row0 = rowBase + wm * 64 + mi * 16 + g8;
        #pragma unroll
        for (int ni = 0; ni < 4; ni++) {
            const int col = colBase + wn * 32 + ni * 8 + 2 * tig;
            *(float2*)&C[(size_t)row0 * N + col] =
                make_float2(acc[mi][ni][0], acc[mi][ni][1]);
            *(float2*)&C[(size_t)(row0 + 8) * N + col] =
                make_float2(acc[mi][ni][2], acc[mi][ni][3]);
        }
    }
}

// ---------------------------------------------------------------------------
// combine1: Hext[z] = split(relu(sum_s g_part1[s][z] + b1)) in ext layout.
// grid (193, 2).  bx==192: Sy finalize.
// ---------------------------------------------------------------------------
__global__ void __launch_bounds__(256)
combine1(const float* __restrict__ mu_b1, const float* __restrict__ lv_b1)
{
    const int z = blockIdx.y;
    const int bx = blockIdx.x;
    const int tid = threadIdx.x;

    if (bx == 192) {
        if (z == 0) {
            #pragma unroll
            for (int j = 0; j < 3; j++) {
                const int d = j * 256 + tid;
                float a = 0.0f, b = 0.0f;
                #pragma unroll
                for (int r = 0; r < 8; r++) { a += g_Syp[r][d]; b += g_Sy2p[r][d]; }
                g_Sy[d] = a;
                g_Sy2[d] = b;
            }
        }
        return;
    }

    const float* __restrict__ bias = z ? lv_b1 : mu_b1;
    constexpr size_t PH4 = (size_t)BB * HH / 4;      // 49152
    const int i4 = bx * 256 + tid;                   // < 49152
    const int row = i4 / 96;
    const int c4 = i4 % 96;
    const int cols = c4 * 4;

    const float4* P = (const float4*)g_part1;
    float4 sv = P[(size_t)(0 * 2 + z) * PH4 + i4];
    #pragma unroll
    for (int sk = 1; sk < 6; sk++) {
        float4 v = P[(size_t)(sk * 2 + z) * PH4 + i4];
        sv.x += v.x; sv.y += v.y; sv.z += v.z; sv.w += v.w;
    }
    const float4 b4 = ((const float4*)bias)[c4];
    float h[4] = {fmaxf(sv.x + b4.x, 0.0f), fmaxf(sv.y + b4.y, 0.0f),
                  fmaxf(sv.z + b4.z, 0.0f), fmaxf(sv.w + b4.w, 0.0f)};

    __nv_bfloat16 hh[4], ll[4];
    #pragma unroll
    for (int i = 0; i < 4; i++) bf16split(h[i], hh[i], ll[i]);

    __nv_bfloat16* R = g_Hext[z] + (size_t)row * KP2;
    __nv_bfloat162 ph0; ph0.x = hh[0]; ph0.y = hh[1];
    __nv_bfloat162 ph1; ph1.x = hh[2]; ph1.y = hh[3];
    __nv_bfloat162 pl0; pl0.x = ll[0]; pl0.y = ll[1];
    __nv_bfloat162 pl1; pl1.x = ll[2]; pl1.y = ll[3];
    ((__nv_bfloat162*)(R + cols))[0] = ph0;          // Hh @ [0,384)
    ((__nv_bfloat162*)(R + cols))[1] = ph1;
    ((__nv_bfloat162*)(R + 384 + cols))[0] = ph0;    // Hh @ [384,768)
    ((__nv_bfloat162*)(R + 384 + cols))[1] = ph1;
    ((__nv_bfloat162*)(R + 768 + cols))[0] = pl0;    // Hl @ [768,1152)
    ((__nv_bfloat162*)(R + 768 + cols))[1] = pl1;
}

// ---------------------------------------------------------------------------
// reduce_final: one float4 per thread (384 x 256 = BB*DD/4 exactly).
// Combines stage-2 partials (+bias, tanh); closed-form sums:
//   pos: -(mu-y)^2/2 * e^{-lv} - lv/2
//   neg: -e^{-lv}/2 * (Sy2 - 2 mu Sy + B mu^2) - B lv / 2
//   out = pos/B - neg/B^2 - log1p(e^{-20}/(B-1))
// ---------------------------------------------------------------------------
__global__ void __launch_bounds__(256)
reduce_final(const float* __restrict__ y,
             const float* __restrict__ mu_b2, const float* __restrict__ lv_b2,
             float* __restrict__ out)
{
    const int tid = threadIdx.x;
    const int g = blockIdx.x * 256 + tid;          // float4 index, < 98304
    const int d4 = g % (DD / 4);

    constexpr size_t PD4 = (size_t)BB * DD / 4;
    const float4* P = (const float4*)g_part2;

    const float4 m0 = P[0 * PD4 + g];
    const float4 m1 = P[2 * PD4 + g];
    const float4 m2 = P[4 * PD4 + g];
    const float4 l0 = P[1 * PD4 + g];
    const float4 l1 = P[3 * PD4 + g];
    const float4 l2 = P[5 * PD4 + g];
    const float4 mb = ((const float4*)mu_b2)[d4];
    const float4 lb = ((const float4*)lv_b2)[d4];
    const float4 y4 = ((const float4*)y)[g];
    const float4 sy = ((const float4*)g_Sy)[d4];
    const float4 s2 = ((const float4*)g_Sy2)[d4];

    float mu[4]  = {m0.x + m1.x + m2.x + mb.x, m0.y + m1.y + m2.y + mb.y,
                    m0.z + m1.z + m2.z + mb.z, m0.w + m1.w + m2.w + mb.w};
    float lv[4]  = {tanhf(l0.x + l1.x + l2.x + lb.x), tanhf(l0.y + l1.y + l2.y + lb.y),
                    tanhf(l0.z + l1.z + l2.z + lb.z), tanhf(l0.w + l1.w + l2.w + lb.w)};
    float yv[4]  = {y4.x, y4.y, y4.z, y4.w};
    float Sy[4]  = {sy.x, sy.y, sy.z, sy.w};
    float Sy2[4] = {s2.x, s2.y, s2.z, s2.w};

    float posf = 0.0f, negf = 0.0f;
    #pragma unroll
    for (int i = 0; i < 4; i++) {
        const float iv = __expf(-lv[i]);
        const float dm = mu[i] - yv[i];
        posf += fmaf(-0.5f * dm * dm, iv, -0.5f * lv[i]);
        const float q = fmaf(fmaf((float)BB, mu[i], -2.0f * Sy[i]), mu[i], Sy2[i]);
        negf += fmaf(-0.5f * iv, q, -(0.5f * (float)BB) * lv[i]);
    }

    __shared__ double sp[256];
    __shared__ double sn[256];
    sp[tid] = (double)posf;
    sn[tid] = (double)negf;
    __syncthreads();
    for (int off = 128; off > 0; off >>= 1) {
        if (tid < off) { sp[tid] += sp[tid + off]; sn[tid] += sn[tid + off]; }
        __syncthreads();
    }
    if (tid == 0) {
        atomicAdd(&g_acc[0], sp[0]);
        atomicAdd(&g_acc[1], sn[0]);
        __threadfence();
        unsigned old = atomicAdd(&g_done, 1u);
        if (old == gridDim.x - 1) {
            g_done = 0u;
            double p = atomicAdd(&g_acc[0], 0.0);
            double n = atomicAdd(&g_acc[1], 0.0);
            const double Cc = log1p(exp(-20.0) / (double)(BB - 1));
            out[0] = (float)(p / (double)BB - n / ((double)BB * (double)BB) - Cc);
        }
    }
}

// g_part layouts: [s][z] flattened as (s*2+z); even = mu path, odd = lv path.

// ---------------------------------------------------------------------------
// Launch: 5 kernels.
// ---------------------------------------------------------------------------
extern "C" void kernel_launch(void* const* d_in, const int* in_sizes, int n_in,
                              void* d_out, int out_size)
{
    const float* x     = (const float*)d_in[0];
    const float* y     = (const float*)d_in[1];
    const float* mu_w1 = (const float*)d_in[2];
    const float* mu_b1 = (const float*)d_in[3];
    const float* mu_w2 = (const float*)d_in[4];
    const float* mu_b2 = (const float*)d_in[5];
    const float* lv_w1 = (const float*)d_in[6];
    const float* lv_b1 = (const float*)d_in[7];
    const float* lv_w2 = (const float*)d_in[8];
    const float* lv_b2 = (const float*)d_in[9];
    float* out = (float*)d_out;

    // prep: bf16 ext splits + W transposes + ystats partials + acc init
    prep<<<1561, 256>>>(x, y, mu_w1, lv_w1, mu_w2, lv_w2);

    // Stage 1: Xext @ W1extT, K'=2304, split-K 6 -> g_part1.  144 CTAs.
    gemm_mma<HH, KP1, 6, 1><<<dim3(3, 24, 2), 256>>>();

    // combine partials + b1 + relu -> Hext ; Sy finalize
    combine1<<<dim3(193, 2), 256>>>(mu_b1, lv_b1);

    // Stage 2: Hext @ W2extT, K'=1152, split-K 3 -> g_part2.  144 CTAs.
    gemm_mma<DD, KP2, 3, 2><<<dim3(6, 12, 2), 256>>>();

    // combine stage-2 partials + bias + tanh + closed-form reduction
    reduce_final<<<384, 256>>>(y, mu_b2, lv_b2, out);
}

// round 12
// speedup vs baseline: 1.0623x; 1.0623x over previous
#include <cuda_runtime.h>
#include <cuda_bf16.h>
#include <math.h>
#include <stdint.h>

#define BB 512
#define DD 768
#define HH 384
#define KP1 2304   // 3 * 768  (extended K for stage 1)
#define KP2 1152   // 3 * 384  (extended K for stage 2)

// -------------------- device scratch (allocation-free rule) -----------------
__device__ __align__(16) __nv_bfloat16 g_Xext[BB * KP1];       // [Xh|Xh|Xl]
__device__ __align__(16) __nv_bfloat16 g_W1T[2][HH * KP1];     // [z][n][Wh|Wl|Wh]
__device__ __align__(16) __nv_bfloat16 g_W2T[2][DD * KP2];     // [z][n][Wh|Wl|Wh]
__device__ __align__(16) __nv_bfloat16 g_Hext[2][BB * KP2];    // [z][Hh|Hh|Hl]
__device__ __align__(16) float g_part1[6 * 2 * BB * HH];       // stage1 split-K partials
__device__ __align__(16) float g_part2[3 * 2 * BB * DD];       // stage2 split-K partials
__device__ __align__(16) float g_Syp[8][DD];
__device__ __align__(16) float g_Sy2p[8][DD];
__device__ __align__(16) float g_Sy[DD];
__device__ __align__(16) float g_Sy2[DD];
__device__ double g_acc[2];
__device__ unsigned g_done;

// -------------------- helpers ----------------------------------------------
__device__ __forceinline__ uint32_t smem_u32(const void* p) {
    uint32_t a;
    asm("{ .reg .u64 t; cvta.to.shared.u64 t, %1; cvt.u32.u64 %0, t; }" : "=r"(a) : "l"(p));
    return a;
}
__device__ __forceinline__ void cp_async16(uint32_t s, const void* g) {
    asm volatile("cp.async.cg.shared.global [%0], [%1], 16;\n" :: "r"(s), "l"(g));
}
__device__ __forceinline__ void cp_commit() { asm volatile("cp.async.commit_group;" ::: "memory"); }
__device__ __forceinline__ void cp_wait0()  { asm volatile("cp.async.wait_group 0;" ::: "memory"); }
__device__ __forceinline__ void cp_wait1()  { asm volatile("cp.async.wait_group 1;" ::: "memory"); }

__device__ __forceinline__ void ldmx4(uint32_t* r, uint32_t addr) {
    asm volatile("ldmatrix.sync.aligned.m8n8.x4.shared.b16 {%0,%1,%2,%3}, [%4];"
                 : "=r"(r[0]), "=r"(r[1]), "=r"(r[2]), "=r"(r[3]) : "r"(addr));
}
__device__ __forceinline__ void mma16816(float* c, const uint32_t* a,
                                         uint32_t b0, uint32_t b1) {
    asm volatile("mma.sync.aligned.m16n8k16.row.col.f32.bf16.bf16.f32 "
                 "{%0,%1,%2,%3}, {%4,%5,%6,%7}, {%8,%9}, {%0,%1,%2,%3};"
                 : "+f"(c[0]), "+f"(c[1]), "+f"(c[2]), "+f"(c[3])
                 : "r"(a[0]), "r"(a[1]), "r"(a[2]), "r"(a[3]), "r"(b0), "r"(b1));
}
__device__ __forceinline__ void bf16split(float v, __nv_bfloat16& h, __nv_bfloat16& l) {
    h = __float2bfloat16(v);
    l = __float2bfloat16(v - __bfloat162float(h));
}

// ---------------------------------------------------------------------------
// prep: Xext split; W1,W2 transpose+split into [N][K'] ext layout;
//       ystats partials; accumulator init.  grid: 1561 x 256.
// ---------------------------------------------------------------------------
__global__ void __launch_bounds__(256)
prep(const float* __restrict__ x, const float* __restrict__ y,
     const float* __restrict__ mu_w1, const float* __restrict__ lv_w1,
     const float* __restrict__ mu_w2, const float* __restrict__ lv_w2)
{
    const int bid = blockIdx.x, tid = threadIdx.x;
    __shared__ float ts[32][33];

    if (bid < 384) {                       // X split: one float4 per thread
        const int i4 = bid * 256 + tid;    // < 98304
        const int row = i4 / 192;
        const int cols = (i4 % 192) * 4;
        float4 v = ((const float4*)x)[i4];
        __nv_bfloat16 h0,l0,h1,l1,h2,l2,h3,l3;
        bf16split(v.x,h0,l0); bf16split(v.y,h1,l1);
        bf16split(v.z,h2,l2); bf16split(v.w,h3,l3);
        __nv_bfloat162 ph0; ph0.x=h0; ph0.y=h1;
        __nv_bfloat162 ph1; ph1.x=h2; ph1.y=h3;
        __nv_bfloat162 pl0; pl0.x=l0; pl0.y=l1;
        __nv_bfloat162 pl1; pl1.x=l2; pl1.y=l3;
        __nv_bfloat16* R = g_Xext + (size_t)row * KP1;
        ((__nv_bfloat162*)(R + cols))[0] = ph0;        // Ah @ [0,768)
        ((__nv_bfloat162*)(R + cols))[1] = ph1;
        ((__nv_bfloat162*)(R + 768 + cols))[0] = ph0;  // Ah @ [768,1536)
        ((__nv_bfloat162*)(R + 768 + cols))[1] = ph1;
        ((__nv_bfloat162*)(R + 1536 + cols))[0] = pl0; // Al @ [1536,2304)
        ((__nv_bfloat162*)(R + 1536 + cols))[1] = pl1;
    } else if (bid < 960) {                // W1 [768k][384n] -> T [384][2304]
        const int t = bid - 384;
        const int z = t / 288, tt = t % 288;
        const int kt = tt / 12, nt = tt % 12;
        const int k0 = kt * 32, n0 = nt * 32;
        const float* W = z ? lv_w1 : mu_w1;
        #pragma unroll
        for (int u = 0; u < 4; u++) {
            int r = (tid >> 5) + u * 8, c = tid & 31;
            ts[r][c] = W[(k0 + r) * HH + n0 + c];
        }
        __syncthreads();
        #pragma unroll
        for (int u = 0; u < 4; u++) {
            int r = (tid >> 5) + u * 8, c = tid & 31;
            __nv_bfloat16 h, l;
            bf16split(ts[c][r], h, l);          // = W[k0+c][n0+r]
            __nv_bfloat16* R = g_W1T[z] + (size_t)(n0 + r) * KP1;
            R[k0 + c] = h;                       // Bh
            R[768 + k0 + c] = l;                 // Bl
            R[1536 + k0 + c] = h;                // Bh
        }
    } else if (bid < 1536) {               // W2 [384k][768n] -> T [768][1152]
        const int t = bid - 960;
        const int z = t / 288, tt = t % 288;
        const int kt = tt / 24, nt = tt % 24;
        const int k0 = kt * 32, n0 = nt * 32;
        const float* W = z ? lv_w2 : mu_w2;
        #pragma unroll
        for (int u = 0; u < 4; u++) {
            int r = (tid >> 5) + u * 8, c = tid & 31;
            ts[r][c] = W[(k0 + r) * DD + n0 + c];
        }
        __syncthreads();
        #pragma unroll
        for (int u = 0; u < 4; u++) {
            int r = (tid >> 5) + u * 8, c = tid & 31;
            __nv_bfloat16 h, l;
            bf16split(ts[c][r], h, l);
            __nv_bfloat16* R = g_W2T[z] + (size_t)(n0 + r) * KP2;
            R[k0 + c] = h;
            R[384 + k0 + c] = l;
            R[768 + k0 + c] = h;
        }
    } else if (bid < 1560) {               // ystats partials: 24 units
        const int unit = bid - 1536;
        const int rc = unit / 3, cb = unit % 3;
        const int d = cb * 256 + tid;
        float s = 0.0f, s2 = 0.0f;
        const int j0 = rc * 64;
        #pragma unroll 4
        for (int j = j0; j < j0 + 64; j++) {
            float v = y[j * DD + d];
            s += v;
            s2 = fmaf(v, v, s2);
        }
        g_Syp[rc][d] = s;
        g_Sy2p[rc][d] = s2;
    } else {
        if (tid == 0) { g_acc[0] = 0.0; g_acc[1] = 0.0; g_done = 0u; }
    }
}

// ---------------------------------------------------------------------------
// bf16 mma.sync GEMM, split-K.  128x128 CTA tile, 512 threads (16 warps),
// warp grid 4x4, warp tile 32x32 (2 x m16, 4 x n8).  K slab = 32,
// cp.async double buffer.  smem rows padded to 80B -> ldmatrix conflict-free.
//   C_part[s][z] = Aext[128 rows] @ BextT[K'-chunk s]   (raw fp32 partials)
// ---------------------------------------------------------------------------
template <int N, int KP, int SK, int STAGE>
__global__ void __launch_bounds__(512)
gemm_mma(void)
{
    constexpr int MT = BB / 128;
    constexpr int CHUNK = KP / SK;          // 384
    constexpr int NSLAB = CHUNK / 32;       // 12
    const int tid = threadIdx.x;
    const int z = blockIdx.z;
    const int mTile = blockIdx.y % MT;
    const int s     = blockIdx.y / MT;
    const int rowBase = mTile * 128;
    const int colBase = blockIdx.x * 128;
    const int kBase   = s * CHUNK;

    const __nv_bfloat16* __restrict__ A =
        (STAGE == 1) ? g_Xext : g_Hext[z];
    const __nv_bfloat16* __restrict__ Bm =
        (STAGE == 1) ? g_W1T[z] : g_W2T[z];
    float* __restrict__ C = (STAGE == 1)
        ? (g_part1 + (size_t)(s * 2 + z) * (BB * HH))
        : (g_part2 + (size_t)(s * 2 + z) * ((size_t)BB * DD));

    __shared__ __align__(16) char sm[2][2][10240];   // [buf][A/B], 80B rows
    const uint32_t sb = smem_u32(sm);

    const int warp = tid >> 5, lane = tid & 31;
    const int wm = warp >> 2, wn = warp & 3;         // warp grid 4x4
    const int g8 = lane >> 2, tig = lane & 3;
    const uint32_t lrow = (uint32_t)((lane & 15) * 80 + (lane >> 4) * 16);

    // cp.async mapping: 1 x 16B for A, 1 x 16B for B per thread per slab
    const int r0 = tid >> 2, sg0 = (tid & 3);

    auto load_slab = [&](int slab, int buf) {
        const int k0 = kBase + slab * 32;
        const uint32_t Ad = sb + buf * 20480;
        const uint32_t Bd = Ad + 10240;
        cp_async16(Ad + r0 * 80 + sg0 * 16, A + (size_t)(rowBase + r0) * KP + k0 + sg0 * 8);
        cp_async16(Bd + r0 * 80 + sg0 * 16, Bm + (size_t)(colBase + r0) * KP + k0 + sg0 * 8);
        cp_commit();
    };

    float acc[2][4][4];
    #pragma unroll
    for (int mi = 0; mi < 2; mi++)
        #pragma unroll
        for (int ni = 0; ni < 4; ni++)
            #pragma unroll
            for (int p = 0; p < 4; p++) acc[mi][ni][p] = 0.0f;

    load_slab(0, 0);

    #pragma unroll 1
    for (int sl = 0; sl < NSLAB; sl++) {
        const int buf = sl & 1;
        if (sl + 1 < NSLAB) { load_slab(sl + 1, buf ^ 1); cp_wait1(); }
        else                { cp_wait0(); }
        __syncthreads();

        const uint32_t Ab = sb + buf * 20480;
        const uint32_t Bb = Ab + 10240;
        #pragma unroll
        for (int t = 0; t < 2; t++) {
            uint32_t a[2][4], b[2][4];
            #pragma unroll
            for (int mi = 0; mi < 2; mi++)
                ldmx4(a[mi], Ab + (uint32_t)((wm * 32 + mi * 16) * 80 + t * 32) + lrow);
            #pragma unroll
            for (int ng = 0; ng < 2; ng++)
                ldmx4(b[ng], Bb + (uint32_t)((wn * 32 + ng * 16) * 80 + t * 32) + lrow);
            #pragma unroll
            for (int mi = 0; mi < 2; mi++) {
                mma16816(acc[mi][0], a[mi], b[0][0], b[0][2]);
                mma16816(acc[mi][1], a[mi], b[0][1], b[0][3]);
                mma16816(acc[mi][2], a[mi], b[1][0], b[1][2]);
                mma16816(acc[mi][3], a[mi], b[1][1], b[1][3]);
            }
        }
        __syncthreads();
    }

    // ---- epilogue: raw fp32 partials ----
    #pragma unroll
    for (int mi = 0; mi < 2; mi++) {
        const int row0 = rowBase + wm * 32 + mi * 16 + g8;
        #pragma unroll
        for (int ni = 0; ni < 4; ni++) {
            const int col = colBase + wn * 32 + ni * 8 + 2 * tig;
            *(float2*)&C[(size_t)row0 * N + col] =
                make_float2(acc[mi][ni][0], acc[mi][ni][1]);
            *(float2*)&C[(size_t)(row0 + 8) * N + col] =
                make_float2(acc[mi][ni][2], acc[mi][ni][3]);
        }
    }
}

// ---------------------------------------------------------------------------
// combine1: Hext[z] = split(relu(sum_s g_part1[s][z] + b1)) in ext layout.
// grid (193, 2).  bx==192: Sy finalize.
// ---------------------------------------------------------------------------
__global__ void __launch_bounds__(256)
combine1(const float* __restrict__ mu_b1, const float* __restrict__ lv_b1)
{
    const int z = blockIdx.y;
    const int bx = blockIdx.x;
    const int tid = threadIdx.x;

    if (bx == 192) {
        if (z == 0) {
            #pragma unroll
            for (int j = 0; j < 3; j++) {
                const int d = j * 256 + tid;
                float a = 0.0f, b = 0.0f;
                #pragma unroll
                for (int r = 0; r < 8; r++) { a += g_Syp[r][d]; b += g_Sy2p[r][d]; }
                g_Sy[d] = a;
                g_Sy2[d] = b;
            }
        }
        return;
    }

    const float* __restrict__ bias = z ? lv_b1 : mu_b1;
    constexpr size_t PH4 = (size_t)BB * HH / 4;      // 49152
    const int i4 = bx * 256 + tid;                   // < 49152
    const int row = i4 / 96;
    const int c4 = i4 % 96;
    const int cols = c4 * 4;

    const float4* P = (const float4*)g_part1;
    float4 sv = P[(size_t)(0 * 2 + z) * PH4 + i4];
    #pragma unroll
    for (int sk = 1; sk < 6; sk++) {
        float4 v = P[(size_t)(sk * 2 + z) * PH4 + i4];
        sv.x += v.x; sv.y += v.y; sv.z += v.z; sv.w += v.w;
    }
    const float4 b4 = ((const float4*)bias)[c4];
    float h[4] = {fmaxf(sv.x + b4.x, 0.0f), fmaxf(sv.y + b4.y, 0.0f),
                  fmaxf(sv.z + b4.z, 0.0f), fmaxf(sv.w + b4.w, 0.0f)};

    __nv_bfloat16 hh[4], ll[4];
    #pragma unroll
    for (int i = 0; i < 4; i++) bf16split(h[i], hh[i], ll[i]);

    __nv_bfloat16* R = g_Hext[z] + (size_t)row * KP2;
    __nv_bfloat162 ph0; ph0.x = hh[0]; ph0.y = hh[1];
    __nv_bfloat162 ph1; ph1.x = hh[2]; ph1.y = hh[3];
    __nv_bfloat162 pl0; pl0.x = ll[0]; pl0.y = ll[1];
    __nv_bfloat162 pl1; pl1.x = ll[2]; pl1.y = ll[3];
    ((__nv_bfloat162*)(R + cols))[0] = ph0;          // Hh @ [0,384)
    ((__nv_bfloat162*)(R + cols))[1] = ph1;
    ((__nv_bfloat162*)(R + 384 + cols))[0] = ph0;    // Hh @ [384,768)
    ((__nv_bfloat162*)(R + 384 + cols))[1] = ph1;
    ((__nv_bfloat162*)(R + 768 + cols))[0] = pl0;    // Hl @ [768,1152)
    ((__nv_bfloat162*)(R + 768 + cols))[1] = pl1;
}

// ---------------------------------------------------------------------------
// reduce_final: one float4 per thread (384 x 256 = BB*DD/4 exactly).
// Combines stage-2 partials (+bias, tanh); closed-form sums:
//   pos: -(mu-y)^2/2 * e^{-lv} - lv/2
//   neg: -e^{-lv}/2 * (Sy2 - 2 mu Sy + B mu^2) - B lv / 2
//   out = pos/B - neg/B^2 - log1p(e^{-20}/(B-1))
// ---------------------------------------------------------------------------
__global__ void __launch_bounds__(256)
reduce_final(const float* __restrict__ y,
             const float* __restrict__ mu_b2, const float* __restrict__ lv_b2,
             float* __restrict__ out)
{
    const int tid = threadIdx.x;
    const int g = blockIdx.x * 256 + tid;          // float4 index, < 98304
    const int d4 = g % (DD / 4);

    constexpr size_t PD4 = (size_t)BB * DD / 4;
    const float4* P = (const float4*)g_part2;

    const float4 m0 = P[0 * PD4 + g];
    const float4 m1 = P[2 * PD4 + g];
    const float4 m2 = P[4 * PD4 + g];
    const float4 l0 = P[1 * PD4 + g];
    const float4 l1 = P[3 * PD4 + g];
    const float4 l2 = P[5 * PD4 + g];
    const float4 mb = ((const float4*)mu_b2)[d4];
    const float4 lb = ((const float4*)lv_b2)[d4];
    const float4 y4 = ((const float4*)y)[g];
    const float4 sy = ((const float4*)g_Sy)[d4];
    const float4 s2 = ((const float4*)g_Sy2)[d4];

    float mu[4]  = {m0.x + m1.x + m2.x + mb.x, m0.y + m1.y + m2.y + mb.y,
                    m0.z + m1.z + m2.z + mb.z, m0.w + m1.w + m2.w + mb.w};
    float lv[4]  = {tanhf(l0.x + l1.x + l2.x + lb.x), tanhf(l0.y + l1.y + l2.y + lb.y),
                    tanhf(l0.z + l1.z + l2.z + lb.z), tanhf(l0.w + l1.w + l2.w + lb.w)};
    float yv[4]  = {y4.x, y4.y, y4.z, y4.w};
    float Sy[4]  = {sy.x, sy.y, sy.z, sy.w};
    float Sy2[4] = {s2.x, s2.y, s2.z, s2.w};

    float posf = 0.0f, negf = 0.0f;
    #pragma unroll
    for (int i = 0; i < 4; i++) {
        const float iv = __expf(-lv[i]);
        const float dm = mu[i] - yv[i];
        posf += fmaf(-0.5f * dm * dm, iv, -0.5f * lv[i]);
        const float q = fmaf(fmaf((float)BB, mu[i], -2.0f * Sy[i]), mu[i], Sy2[i]);
        negf += fmaf(-0.5f * iv, q, -(0.5f * (float)BB) * lv[i]);
    }

    __shared__ double sp[256];
    __shared__ double sn[256];
    sp[tid] = (double)posf;
    sn[tid] = (double)negf;
    __syncthreads();
    for (int off = 128; off > 0; off >>= 1) {
        if (tid < off) { sp[tid] += sp[tid + off]; sn[tid] += sn[tid + off]; }
        __syncthreads();
    }
    if (tid == 0) {
        atomicAdd(&g_acc[0], sp[0]);
        atomicAdd(&g_acc[1], sn[0]);
        __threadfence();
        unsigned old = atomicAdd(&g_done, 1u);
        if (old == gridDim.x - 1) {
            g_done = 0u;
            double p = atomicAdd(&g_acc[0], 0.0);
            double n = atomicAdd(&g_acc[1], 0.0);
            const double Cc = log1p(exp(-20.0) / (double)(BB - 1));
            out[0] = (float)(p / (double)BB - n / ((double)BB * (double)BB) - Cc);
        }
    }
}

// g_part layouts: [s][z] flattened as (s*2+z); even = mu path, odd = lv path.

// ---------------------------------------------------------------------------
// Launch: 5 kernels.
// ---------------------------------------------------------------------------
extern "C" void kernel_launch(void* const* d_in, const int* in_sizes, int n_in,
                              void* d_out, int out_size)
{
    const float* x     = (const float*)d_in[0];
    const float* y     = (const float*)d_in[1];
    const float* mu_w1 = (const float*)d_in[2];
    const float* mu_b1 = (const float*)d_in[3];
    const float* mu_w2 = (const float*)d_in[4];
    const float* mu_b2 = (const float*)d_in[5];
    const float* lv_w1 = (const float*)d_in[6];
    const float* lv_b1 = (const float*)d_in[7];
    const float* lv_w2 = (const float*)d_in[8];
    const float* lv_b2 = (const float*)d_in[9];
    float* out = (float*)d_out;

    // prep: bf16 ext splits + W transposes + ystats partials + acc init
    prep<<<1561, 256>>>(x, y, mu_w1, lv_w1, mu_w2, lv_w2);

    // Stage 1: Xext @ W1extT, K'=2304, split-K 6 -> g_part1.  144 CTAs.
    gemm_mma<HH, KP1, 6, 1><<<dim3(3, 24, 2), 512>>>();

    // combine partials + b1 + relu -> Hext ; Sy finalize
    combine1<<<dim3(193, 2), 256>>>(mu_b1, lv_b1);

    // Stage 2: Hext @ W2extT, K'=1152, split-K 3 -> g_part2.  144 CTAs.
    gemm_mma<DD, KP2, 3, 2><<<dim3(6, 12, 2), 512>>>();

    // combine stage-2 partials + bias + tanh + closed-form reduction
    reduce_final<<<384, 256>>>(y, mu_b2, lv_b2, out);
}

// round 13
// speedup vs baseline: 1.0632x; 1.0008x over previous
#include <cuda_runtime.h>
#include <cuda_bf16.h>
#include <math.h>
#include <stdint.h>

#define BB 512
#define DD 768
#define HH 384
#define KP1 2304   // 3 * 768  (extended K for stage 1)
#define KP2 1152   // 3 * 384  (extended K for stage 2)

// -------------------- device scratch (allocation-free rule) -----------------
__device__ __align__(16) __nv_bfloat16 g_Xext[BB * KP1];       // [Xh|Xh|Xl]
__device__ __align__(16) __nv_bfloat16 g_W1T[2][HH * KP1];     // [z][n][Wh|Wl|Wh]
__device__ __align__(16) __nv_bfloat16 g_W2T[2][DD * KP2];     // [z][n][Wh|Wl|Wh]
__device__ __align__(16) __nv_bfloat16 g_Hext[2][BB * KP2];    // [z][Hh|Hh|Hl]
__device__ __align__(16) float g_part1[6 * 2 * BB * HH];       // stage1 split-K partials
__device__ __align__(16) float g_part2[3 * 2 * BB * DD];       // stage2 split-K partials
__device__ __align__(16) float g_Syp[8][DD];
__device__ __align__(16) float g_Sy2p[8][DD];
__device__ __align__(16) float g_Sy[DD];
__device__ __align__(16) float g_Sy2[DD];
__device__ double g_acc[2];
__device__ unsigned g_done;

// -------------------- helpers ----------------------------------------------
__device__ __forceinline__ uint32_t smem_u32(const void* p) {
    uint32_t a;
    asm("{ .reg .u64 t; cvta.to.shared.u64 t, %1; cvt.u32.u64 %0, t; }" : "=r"(a) : "l"(p));
    return a;
}
__device__ __forceinline__ void cp_async16(uint32_t s, const void* g) {
    asm volatile("cp.async.cg.shared.global [%0], [%1], 16;\n" :: "r"(s), "l"(g));
}
__device__ __forceinline__ void cp_commit() { asm volatile("cp.async.commit_group;" ::: "memory"); }
__device__ __forceinline__ void cp_wait0()  { asm volatile("cp.async.wait_group 0;" ::: "memory"); }

__device__ __forceinline__ void ldmx4(uint32_t* r, uint32_t addr) {
    asm volatile("ldmatrix.sync.aligned.m8n8.x4.shared.b16 {%0,%1,%2,%3}, [%4];"
                 : "=r"(r[0]), "=r"(r[1]), "=r"(r[2]), "=r"(r[3]) : "r"(addr));
}
__device__ __forceinline__ void mma16816(float* c, const uint32_t* a,
                                         uint32_t b0, uint32_t b1) {
    asm volatile("mma.sync.aligned.m16n8k16.row.col.f32.bf16.bf16.f32 "
                 "{%0,%1,%2,%3}, {%4,%5,%6,%7}, {%8,%9}, {%0,%1,%2,%3};"
                 : "+f"(c[0]), "+f"(c[1]), "+f"(c[2]), "+f"(c[3])
                 : "r"(a[0]), "r"(a[1]), "r"(a[2]), "r"(a[3]), "r"(b0), "r"(b1));
}
__device__ __forceinline__ void bf16split(float v, __nv_bfloat16& h, __nv_bfloat16& l) {
    h = __float2bfloat16(v);
    l = __float2bfloat16(v - __bfloat162float(h));
}

// ---------------------------------------------------------------------------
// prep: Xext split; W1,W2 transpose+split into [N][K'] ext layout;
//       ystats partials; accumulator init.  grid: 1561 x 256.
// ---------------------------------------------------------------------------
__global__ void __launch_bounds__(256)
prep(const float* __restrict__ x, const float* __restrict__ y,
     const float* __restrict__ mu_w1, const float* __restrict__ lv_w1,
     const float* __restrict__ mu_w2, const float* __restrict__ lv_w2)
{
    const int bid = blockIdx.x, tid = threadIdx.x;
    __shared__ float ts[32][33];

    if (bid < 384) {                       // X split: one float4 per thread
        const int i4 = bid * 256 + tid;    // < 98304
        const int row = i4 / 192;
        const int cols = (i4 % 192) * 4;
        float4 v = ((const float4*)x)[i4];
        __nv_bfloat16 h0,l0,h1,l1,h2,l2,h3,l3;
        bf16split(v.x,h0,l0); bf16split(v.y,h1,l1);
        bf16split(v.z,h2,l2); bf16split(v.w,h3,l3);
        __nv_bfloat162 ph0; ph0.x=h0; ph0.y=h1;
        __nv_bfloat162 ph1; ph1.x=h2; ph1.y=h3;
        __nv_bfloat162 pl0; pl0.x=l0; pl0.y=l1;
        __nv_bfloat162 pl1; pl1.x=l2; pl1.y=l3;
        __nv_bfloat16* R = g_Xext + (size_t)row * KP1;
        ((__nv_bfloat162*)(R + cols))[0] = ph0;        // Ah @ [0,768)
        ((__nv_bfloat162*)(R + cols))[1] = ph1;
        ((__nv_bfloat162*)(R + 768 + cols))[0] = ph0;  // Ah @ [768,1536)
        ((__nv_bfloat162*)(R + 768 + cols))[1] = ph1;
        ((__nv_bfloat162*)(R + 1536 + cols))[0] = pl0; // Al @ [1536,2304)
        ((__nv_bfloat162*)(R + 1536 + cols))[1] = pl1;
    } else if (bid < 960) {                // W1 [768k][384n] -> T [384][2304]
        const int t = bid - 384;
        const int z = t / 288, tt = t % 288;
        const int kt = tt / 12, nt = tt % 12;
        const int k0 = kt * 32, n0 = nt * 32;
        const float* W = z ? lv_w1 : mu_w1;
        #pragma unroll
        for (int u = 0; u < 4; u++) {
            int r = (tid >> 5) + u * 8, c = tid & 31;
            ts[r][c] = W[(k0 + r) * HH + n0 + c];
        }
        __syncthreads();
        #pragma unroll
        for (int u = 0; u < 4; u++) {
            int r = (tid >> 5) + u * 8, c = tid & 31;
            __nv_bfloat16 h, l;
            bf16split(ts[c][r], h, l);          // = W[k0+c][n0+r]
            __nv_bfloat16* R = g_W1T[z] + (size_t)(n0 + r) * KP1;
            R[k0 + c] = h;                       // Bh
            R[768 + k0 + c] = l;                 // Bl
            R[1536 + k0 + c] = h;                // Bh
        }
    } else if (bid < 1536) {               // W2 [384k][768n] -> T [768][1152]
        const int t = bid - 960;
        const int z = t / 288, tt = t % 288;
        const int kt = tt / 24, nt = tt % 24;
        const int k0 = kt * 32, n0 = nt * 32;
        const float* W = z ? lv_w2 : mu_w2;
        #pragma unroll
        for (int u = 0; u < 4; u++) {
            int r = (tid >> 5) + u * 8, c = tid & 31;
            ts[r][c] = W[(k0 + r) * DD + n0 + c];
        }
        __syncthreads();
        #pragma unroll
        for (int u = 0; u < 4; u++) {
            int r = (tid >> 5) + u * 8, c = tid & 31;
            __nv_bfloat16 h, l;
            bf16split(ts[c][r], h, l);
            __nv_bfloat16* R = g_W2T[z] + (size_t)(n0 + r) * KP2;
            R[k0 + c] = h;
            R[384 + k0 + c] = l;
            R[768 + k0 + c] = h;
        }
    } else if (bid < 1560) {               // ystats partials: 24 units
        const int unit = bid - 1536;
        const int rc = unit / 3, cb = unit % 3;
        const int d = cb * 256 + tid;
        float s = 0.0f, s2 = 0.0f;
        const int j0 = rc * 64;
        #pragma unroll 4
        for (int j = j0; j < j0 + 64; j++) {
            float v = y[j * DD + d];
            s += v;
            s2 = fmaf(v, v, s2);
        }
        g_Syp[rc][d] = s;
        g_Sy2p[rc][d] = s2;
    } else {
        if (tid == 0) { g_acc[0] = 0.0; g_acc[1] = 0.0; g_done = 0u; }
    }
}

// ---------------------------------------------------------------------------
// bf16 mma.sync GEMM, split-K.  128x128 CTA tile, 512 threads (16 warps),
// warp grid 4x4, warp tile 32x32 (2 x m16, 4 x n8).  K slab = 32,
// cp.async double buffer, ONE __syncthreads per slab, all ldmatrix
// fragments for the slab issued before the mma burst (latency covered once).
//   C_part[s][z] = Aext[128 rows] @ BextT[K'-chunk s]   (raw fp32 partials)
// smem rows padded to 80B -> ldmatrix conflict-free.
// ---------------------------------------------------------------------------
template <int N, int KP, int SK, int STAGE>
__global__ void __launch_bounds__(512)
gemm_mma(void)
{
    constexpr int MT = BB / 128;
    constexpr int CHUNK = KP / SK;          // 384
    constexpr int NSLAB = CHUNK / 32;       // 12
    const int tid = threadIdx.x;
    const int z = blockIdx.z;
    const int mTile = blockIdx.y % MT;
    const int s     = blockIdx.y / MT;
    const int rowBase = mTile * 128;
    const int colBase = blockIdx.x * 128;
    const int kBase   = s * CHUNK;

    const __nv_bfloat16* __restrict__ A =
        (STAGE == 1) ? g_Xext : g_Hext[z];
    const __nv_bfloat16* __restrict__ Bm =
        (STAGE == 1) ? g_W1T[z] : g_W2T[z];
    float* __restrict__ C = (STAGE == 1)
        ? (g_part1 + (size_t)(s * 2 + z) * (BB * HH))
        : (g_part2 + (size_t)(s * 2 + z) * ((size_t)BB * DD));

    __shared__ __align__(16) char sm[2][2][10240];   // [buf][A/B], 80B rows
    const uint32_t sb = smem_u32(sm);

    const int warp = tid >> 5, lane = tid & 31;
    const int wm = warp >> 2, wn = warp & 3;         // warp grid 4x4
    const int g8 = lane >> 2, tig = lane & 3;
    const uint32_t lrow = (uint32_t)((lane & 15) * 80 + (lane >> 4) * 16);

    // cp.async mapping: 1 x 16B for A, 1 x 16B for B per thread per slab
    const int r0 = tid >> 2, sg0 = (tid & 3);

    auto load_slab = [&](int slab, int buf) {
        const int k0 = kBase + slab * 32;
        const uint32_t Ad = sb + buf * 20480;
        const uint32_t Bd = Ad + 10240;
        cp_async16(Ad + r0 * 80 + sg0 * 16, A + (size_t)(rowBase + r0) * KP + k0 + sg0 * 8);
        cp_async16(Bd + r0 * 80 + sg0 * 16, Bm + (size_t)(colBase + r0) * KP + k0 + sg0 * 8);
        cp_commit();
    };

    float acc[2][4][4];
    #pragma unroll
    for (int mi = 0; mi < 2; mi++)
        #pragma unroll
        for (int ni = 0; ni < 4; ni++)
            #pragma unroll
            for (int p = 0; p < 4; p++) acc[mi][ni][p] = 0.0f;

    load_slab(0, 0);

    #pragma unroll 1
    for (int sl = 0; sl < NSLAB; sl++) {
        const int buf = sl & 1;
        cp_wait0();                // load(sl) arrived
        __syncthreads();           // + all warps done computing buf^1 (slab sl-1)
        if (sl + 1 < NSLAB) load_slab(sl + 1, buf ^ 1);

        const uint32_t Ab = sb + buf * 20480;
        const uint32_t Bb = Ab + 10240;

        // ---- issue ALL fragment loads for the slab (both k-halves) ----
        uint32_t a[2][2][4], b[2][2][4];   // [t][mi/ng][4]
        #pragma unroll
        for (int t = 0; t < 2; t++) {
            #pragma unroll
            for (int mi = 0; mi < 2; mi++)
                ldmx4(a[t][mi], Ab + (uint32_t)((wm * 32 + mi * 16) * 80 + t * 32) + lrow);
            #pragma unroll
            for (int ng = 0; ng < 2; ng++)
                ldmx4(b[t][ng], Bb + (uint32_t)((wn * 32 + ng * 16) * 80 + t * 32) + lrow);
        }
        // ---- mma burst ----
        #pragma unroll
        for (int t = 0; t < 2; t++) {
            #pragma unroll
            for (int mi = 0; mi < 2; mi++) {
                mma16816(acc[mi][0], a[t][mi], b[t][0][0], b[t][0][2]);
                mma16816(acc[mi][1], a[t][mi], b[t][0][1], b[t][0][3]);
                mma16816(acc[mi][2], a[t][mi], b[t][1][0], b[t][1][2]);
                mma16816(acc[mi][3], a[t][mi], b[t][1][1], b[t][1][3]);
            }
        }
    }

    // ---- epilogue: raw fp32 partials ----
    #pragma unroll
    for (int mi = 0; mi < 2; mi++) {
        const int row0 = rowBase + wm * 32 + mi * 16 + g8;
        #pragma unroll
        for (int ni = 0; ni < 4; ni++) {
            const int col = colBase + wn * 32 + ni * 8 + 2 * tig;
            *(float2*)&C[(size_t)row0 * N + col] =
                make_float2(acc[mi][ni][0], acc[mi][ni][1]);
            *(float2*)&C[(size_t)(row0 + 8) * N + col] =
                make_float2(acc[mi][ni][2], acc[mi][ni][3]);
        }
    }
}

// ---------------------------------------------------------------------------
// combine1: Hext[z] = split(relu(sum_s g_part1[s][z] + b1)) in ext layout.
// grid (193, 2).  bx==192: Sy finalize.
// ---------------------------------------------------------------------------
__global__ void __launch_bounds__(256)
combine1(const float* __restrict__ mu_b1, const float* __restrict__ lv_b1)
{
    const int z = blockIdx.y;
    const int bx = blockIdx.x;
    const int tid = threadIdx.x;

    if (bx == 192) {
        if (z == 0) {
            #pragma unroll
            for (int j = 0; j < 3; j++) {
                const int d = j * 256 + tid;
                float a = 0.0f, b = 0.0f;
                #pragma unroll
                for (int r = 0; r < 8; r++) { a += g_Syp[r][d]; b += g_Sy2p[r][d]; }
                g_Sy[d] = a;
                g_Sy2[d] = b;
            }
        }
        return;
    }

    const float* __restrict__ bias = z ? lv_b1 : mu_b1;
    constexpr size_t PH4 = (size_t)BB * HH / 4;      // 49152
    const int i4 = bx * 256 + tid;                   // < 49152
    const int row = i4 / 96;
    const int c4 = i4 % 96;
    const int cols = c4 * 4;

    const float4* P = (const float4*)g_part1;
    float4 sv = P[(size_t)(0 * 2 + z) * PH4 + i4];
    #pragma unroll
    for (int sk = 1; sk < 6; sk++) {
        float4 v = P[(size_t)(sk * 2 + z) * PH4 + i4];
        sv.x += v.x; sv.y += v.y; sv.z += v.z; sv.w += v.w;
    }
    const float4 b4 = ((const float4*)bias)[c4];
    float h[4] = {fmaxf(sv.x + b4.x, 0.0f), fmaxf(sv.y + b4.y, 0.0f),
                  fmaxf(sv.z + b4.z, 0.0f), fmaxf(sv.w + b4.w, 0.0f)};

    __nv_bfloat16 hh[4], ll[4];
    #pragma unroll
    for (int i = 0; i < 4; i++) bf16split(h[i], hh[i], ll[i]);

    __nv_bfloat16* R = g_Hext[z] + (size_t)row * KP2;
    __nv_bfloat162 ph0; ph0.x = hh[0]; ph0.y = hh[1];
    __nv_bfloat162 ph1; ph1.x = hh[2]; ph1.y = hh[3];
    __nv_bfloat162 pl0; pl0.x = ll[0]; pl0.y = ll[1];
    __nv_bfloat162 pl1; pl1.x = ll[2]; pl1.y = ll[3];
    ((__nv_bfloat162*)(R + cols))[0] = ph0;          // Hh @ [0,384)
    ((__nv_bfloat162*)(R + cols))[1] = ph1;
    ((__nv_bfloat162*)(R + 384 + cols))[0] = ph0;    // Hh @ [384,768)
    ((__nv_bfloat162*)(R + 384 + cols))[1] = ph1;
    ((__nv_bfloat162*)(R + 768 + cols))[0] = pl0;    // Hl @ [768,1152)
    ((__nv_bfloat162*)(R + 768 + cols))[1] = pl1;
}

// ---------------------------------------------------------------------------
// reduce_final: one float4 per thread (384 x 256 = BB*DD/4 exactly).
// Combines stage-2 partials (+bias, tanh); closed-form sums:
//   pos: -(mu-y)^2/2 * e^{-lv} - lv/2
//   neg: -e^{-lv}/2 * (Sy2 - 2 mu Sy + B mu^2) - B lv / 2
//   out = pos/B - neg/B^2 - log1p(e^{-20}/(B-1))
// ---------------------------------------------------------------------------
__global__ void __launch_bounds__(256)
reduce_final(const float* __restrict__ y,
             const float* __restrict__ mu_b2, const float* __restrict__ lv_b2,
             float* __restrict__ out)
{
    const int tid = threadIdx.x;
    const int g = blockIdx.x * 256 + tid;          // float4 index, < 98304
    const int d4 = g % (DD / 4);

    constexpr size_t PD4 = (size_t)BB * DD / 4;
    const float4* P = (const float4*)g_part2;

    const float4 m0 = P[0 * PD4 + g];
    const float4 m1 = P[2 * PD4 + g];
    const float4 m2 = P[4 * PD4 + g];
    const float4 l0 = P[1 * PD4 + g];
    const float4 l1 = P[3 * PD4 + g];
    const float4 l2 = P[5 * PD4 + g];
    const float4 mb = ((const float4*)mu_b2)[d4];
    const float4 lb = ((const float4*)lv_b2)[d4];
    const float4 y4 = ((const float4*)y)[g];
    const float4 sy = ((const float4*)g_Sy)[d4];
    const float4 s2 = ((const float4*)g_Sy2)[d4];

    float mu[4]  = {m0.x + m1.x + m2.x + mb.x, m0.y + m1.y + m2.y + mb.y,
                    m0.z + m1.z + m2.z + mb.z, m0.w + m1.w + m2.w + mb.w};
    float lv[4]  = {tanhf(l0.x + l1.x + l2.x + lb.x), tanhf(l0.y + l1.y + l2.y + lb.y),
                    tanhf(l0.z + l1.z + l2.z + lb.z), tanhf(l0.w + l1.w + l2.w + lb.w)};
    float yv[4]  = {y4.x, y4.y, y4.z, y4.w};
    float Sy[4]  = {sy.x, sy.y, sy.z, sy.w};
    float Sy2[4] = {s2.x, s2.y, s2.z, s2.w};

    float posf = 0.0f, negf = 0.0f;
    #pragma unroll
    for (int i = 0; i < 4; i++) {
        const float iv = __expf(-lv[i]);
        const float dm = mu[i] - yv[i];
        posf += fmaf(-0.5f * dm * dm, iv, -0.5f * lv[i]);
        const float q = fmaf(fmaf((float)BB, mu[i], -2.0f * Sy[i]), mu[i], Sy2[i]);
        negf += fmaf(-0.5f * iv, q, -(0.5f * (float)BB) * lv[i]);
    }

    __shared__ double sp[256];
    __shared__ double sn[256];
    sp[tid] = (double)posf;
    sn[tid] = (double)negf;
    __syncthreads();
    for (int off = 128; off > 0; off >>= 1) {
        if (tid < off) { sp[tid] += sp[tid + off]; sn[tid] += sn[tid + off]; }
        __syncthreads();
    }
    if (tid == 0) {
        atomicAdd(&g_acc[0], sp[0]);
        atomicAdd(&g_acc[1], sn[0]);
        __threadfence();
        unsigned old = atomicAdd(&g_done, 1u);
        if (old == gridDim.x - 1) {
            g_done = 0u;
            double p = atomicAdd(&g_acc[0], 0.0);
            double n = atomicAdd(&g_acc[1], 0.0);
            const double Cc = log1p(exp(-20.0) / (double)(BB - 1));
            out[0] = (float)(p / (double)BB - n / ((double)BB * (double)BB) - Cc);
        }
    }
}

// g_part layouts: [s][z] flattened as (s*2+z); even = mu path, odd = lv path.

// ---------------------------------------------------------------------------
// Launch: 5 kernels.
// ---------------------------------------------------------------------------
extern "C" void kernel_launch(void* const* d_in, const int* in_sizes, int n_in,
                              void* d_out, int out_size)
{
    const float* x     = (const float*)d_in[0];
    const float* y     = (const float*)d_in[1];
    const float* mu_w1 = (const float*)d_in[2];
    const float* mu_b1 = (const float*)d_in[3];
    const float* mu_w2 = (const float*)d_in[4];
    const float* mu_b2 = (const float*)d_in[5];
    const float* lv_w1 = (const float*)d_in[6];
    const float* lv_b1 = (const float*)d_in[7];
    const float* lv_w2 = (const float*)d_in[8];
    const float* lv_b2 = (const float*)d_in[9];
    float* out = (float*)d_out;

    // prep: bf16 ext splits + W transposes + ystats partials + acc init
    prep<<<1561, 256>>>(x, y, mu_w1, lv_w1, mu_w2, lv_w2);

    // Stage 1: Xext @ W1extT, K'=2304, split-K 6 -> g_part1.  144 CTAs.
    gemm_mma<HH, KP1, 6, 1><<<dim3(3, 24, 2), 512>>>();

    // combine partials + b1 + relu -> Hext ; Sy finalize
    combine1<<<dim3(193, 2), 256>>>(mu_b1, lv_b1);

    // Stage 2: Hext @ W2extT, K'=1152, split-K 3 -> g_part2.  144 CTAs.
    gemm_mma<DD, KP2, 3, 2><<<dim3(6, 12, 2), 512>>>();

    // combine stage-2 partials + bias + tanh + closed-form reduction
    reduce_final<<<384, 256>>>(y, mu_b2, lv_b2, out);
}